// round 1
// baseline (speedup 1.0000x reference)
#include <cuda_runtime.h>
#include <math.h>

// Problem constants
#define BB 2
#define SS 2048
#define EE 1024
#define HH 16
#define DD 64

// ---------------------------------------------------------------------------
// Scratch (device globals — no allocation allowed)
// ---------------------------------------------------------------------------
__device__ float g_q[BB*HH*SS*DD];     // [b][h][s][d]
__device__ float g_k[BB*HH*SS*DD];
__device__ float g_v[BB*HH*SS*DD];
__device__ float g_ctx[BB*SS*EE];      // attention output in [b][s][e] layout
__device__ float g_bias8[HH*SS];       // rel_bias[bucket(dist)][h] * 8

// ---------------------------------------------------------------------------
// Kernel 1: precompute position bias table bias8[h][dist], dist in [0,2048)
// Matches reference float32 math exactly (logf, f32 log(4) constant, trunc).
// ---------------------------------------------------------------------------
__global__ void bias_kernel(const float* __restrict__ rel_bias) {
    int idx = blockIdx.x * blockDim.x + threadIdx.x;   // h*SS + dist
    if (idx >= HH * SS) return;
    int h = idx / SS;
    int d = idx % SS;
    int bucket;
    if (d < 16) {
        bucket = d;
    } else {
        float rp = (float)d;
        // (log(rp/16) / log(4)) * 16, all float32, then trunc toward zero
        float t = (logf(rp * 0.0625f) / 1.3862943611198906f) * 16.0f;
        int lb = 16 + (int)t;
        bucket = lb < 31 ? lb : 31;
    }
    g_bias8[idx] = rel_bias[bucket * HH + h] * 8.0f;
}

// ---------------------------------------------------------------------------
// Kernel 2: tiled fp32 GEMM  C[M=4096,N=1024] = A @ W + bias
//   mode 0: A = g_ctx (internal), C -> Cout natural [m][n]       (O-proj)
//   mode 1/2/3: A = param, C scattered to g_q/g_k/g_v [b][h][s][d] (QKV)
// ---------------------------------------------------------------------------
#define GBM 128
#define GBN 64
#define GBK 16

__global__ __launch_bounds__(256)
void gemm_kernel(const float* __restrict__ Ain, const float* __restrict__ W,
                 const float* __restrict__ bias, float* __restrict__ Cout,
                 int mode) {
    __shared__ float As[GBM][GBK];        // [m][k], float4-aligned rows
    __shared__ float Bs[GBK][GBN + 4];    // [k][n], padded stride 68

    const float* A = (mode == 0) ? g_ctx : Ain;

    int tid = threadIdx.x;
    int tx = tid & 15;          // n-group (4 cols)
    int ty = tid >> 4;          // m-group (8 rows)
    int m0 = blockIdx.y * GBM;
    int n0 = blockIdx.x * GBN;

    float acc[8][4];
#pragma unroll
    for (int i = 0; i < 8; i++)
#pragma unroll
        for (int j = 0; j < 4; j++) acc[i][j] = 0.f;

    for (int k0 = 0; k0 < EE; k0 += GBK) {
        // load A tile: 128x16 = 512 float4, 2 per thread
#pragma unroll
        for (int it = 0; it < 2; it++) {
            int idx = tid + it * 256;
            int m = idx >> 2;
            int k4 = idx & 3;
            float4 v = *(const float4*)&A[(size_t)(m0 + m) * EE + k0 + k4 * 4];
            *(float4*)&As[m][k4 * 4] = v;
        }
        // load B tile: 16x64 = 256 float4, 1 per thread
        {
            int kk = tid >> 4;
            int n4 = tid & 15;
            float4 v = *(const float4*)&W[(size_t)(k0 + kk) * EE + n0 + n4 * 4];
            *(float4*)&Bs[kk][n4 * 4] = v;
        }
        __syncthreads();

#pragma unroll
        for (int kk = 0; kk < GBK; kk++) {
            float4 bv = *(const float4*)&Bs[kk][tx * 4];
#pragma unroll
            for (int i = 0; i < 8; i++) {
                float a = As[ty * 8 + i][kk];
                acc[i][0] += a * bv.x;
                acc[i][1] += a * bv.y;
                acc[i][2] += a * bv.z;
                acc[i][3] += a * bv.w;
            }
        }
        __syncthreads();
    }

    // epilogue
#pragma unroll
    for (int i = 0; i < 8; i++) {
        int m = m0 + ty * 8 + i;
        int bidx = m >> 11;       // /2048
        int srow = m & 2047;
#pragma unroll
        for (int j = 0; j < 4; j++) {
            int n = n0 + tx * 4 + j;
            float val = acc[i][j] + bias[n];
            if (mode == 0) {
                Cout[(size_t)m * EE + n] = val;
            } else {
                int h = n >> 6, d = n & 63;
                float* dst = (mode == 1) ? g_q : (mode == 2) ? g_k : g_v;
                dst[(((size_t)bidx * HH + h) * SS + srow) * DD + d] = val;
            }
        }
    }
}

// ---------------------------------------------------------------------------
// Kernel 3: flash attention fp32, per-CTA: one (b, h, 64-row q tile)
//   smem: Qs[64][68] | Kt[64][68] (d-major K, aliased by Ps) | Vs[64][68]
// ---------------------------------------------------------------------------
#define ASTRIDE 68
#define ATTN_SMEM (3 * 64 * ASTRIDE * 4)

__global__ __launch_bounds__(256)
void attn_kernel() {
    extern __shared__ float smem[];
    float* Qs = smem;                        // [row][d], stride 68
    float* Kt = smem + 64 * ASTRIDE;         // [d][kcol], stride 68 (aliased as Ps)
    float* Vs = smem + 2 * 64 * ASTRIDE;     // [kpos][d], stride 68
    float* Ps = Kt;                          // [row][kpos], stride 68

    int qt = blockIdx.x;     // q tile 0..31
    int h  = blockIdx.y;
    int b  = blockIdx.z;
    int tid = threadIdx.x;
    int tx = tid & 15, ty = tid >> 4;
    int i0 = ty * 4, j0 = tx * 4;
    int qbase = qt * 64;

    const float* Qg = g_q + (((size_t)b * HH + h) * SS + qbase) * DD;
    const float* Kg = g_k + (((size_t)b * HH + h) * SS) * DD;
    const float* Vg = g_v + (((size_t)b * HH + h) * SS) * DD;
    const float* biasrow = g_bias8 + h * SS;

    // load Q tile, pre-scaled by 1/sqrt(D)=0.125
#pragma unroll
    for (int it = 0; it < 4; it++) {
        int idx = tid + it * 256;   // 0..1023 float4
        int r = idx >> 4;
        int c4 = idx & 15;
        float4 v = *(const float4*)&Qg[r * 64 + c4 * 4];
        v.x *= 0.125f; v.y *= 0.125f; v.z *= 0.125f; v.w *= 0.125f;
        *(float4*)&Qs[r * ASTRIDE + c4 * 4] = v;
    }

    float m_i[4], l_i[4], acc[4][4];
#pragma unroll
    for (int i = 0; i < 4; i++) {
        m_i[i] = -1e30f; l_i[i] = 0.f;
#pragma unroll
        for (int j = 0; j < 4; j++) acc[i][j] = 0.f;
    }

    for (int kt = 0; kt < 32; kt++) {
        __syncthreads();   // prior-iter Ps/Vs reads done; also covers Q stores on iter 0
        // load K tile transposed (d-major) and V tile natural
#pragma unroll
        for (int it = 0; it < 4; it++) {
            int idx = tid + it * 256;
            int r = idx >> 4;
            int c4 = idx & 15;
            float4 kv = *(const float4*)&Kg[(size_t)(kt * 64 + r) * 64 + c4 * 4];
            Kt[(c4 * 4 + 0) * ASTRIDE + r] = kv.x;
            Kt[(c4 * 4 + 1) * ASTRIDE + r] = kv.y;
            Kt[(c4 * 4 + 2) * ASTRIDE + r] = kv.z;
            Kt[(c4 * 4 + 3) * ASTRIDE + r] = kv.w;
            float4 vv = *(const float4*)&Vg[(size_t)(kt * 64 + r) * 64 + c4 * 4];
            *(float4*)&Vs[r * ASTRIDE + c4 * 4] = vv;
        }
        __syncthreads();

        // S = (Q*scale) @ K^T
        float s[4][4];
#pragma unroll
        for (int i = 0; i < 4; i++)
#pragma unroll
            for (int j = 0; j < 4; j++) s[i][j] = 0.f;

#pragma unroll 4
        for (int d = 0; d < 64; d++) {
            float4 kf = *(const float4*)&Kt[d * ASTRIDE + j0];
            float q0 = Qs[(i0 + 0) * ASTRIDE + d];
            float q1 = Qs[(i0 + 1) * ASTRIDE + d];
            float q2 = Qs[(i0 + 2) * ASTRIDE + d];
            float q3 = Qs[(i0 + 3) * ASTRIDE + d];
            s[0][0] += q0 * kf.x; s[0][1] += q0 * kf.y; s[0][2] += q0 * kf.z; s[0][3] += q0 * kf.w;
            s[1][0] += q1 * kf.x; s[1][1] += q1 * kf.y; s[1][2] += q1 * kf.z; s[1][3] += q1 * kf.w;
            s[2][0] += q2 * kf.x; s[2][1] += q2 * kf.y; s[2][2] += q2 * kf.z; s[2][3] += q2 * kf.w;
            s[3][0] += q3 * kf.x; s[3][1] += q3 * kf.y; s[3][2] += q3 * kf.z; s[3][3] += q3 * kf.w;
        }

        // add relative-position bias
#pragma unroll
        for (int i = 0; i < 4; i++) {
            int qrow = qbase + i0 + i;
#pragma unroll
            for (int j = 0; j < 4; j++) {
                int dist = qrow - (kt * 64 + j0 + j);
                if (dist < 0) dist = 0;
                s[i][j] += biasrow[dist];
            }
        }

        // online softmax update (rows shared by 16 lanes -> width-16 shuffles)
#pragma unroll
        for (int i = 0; i < 4; i++) {
            float mt = fmaxf(fmaxf(s[i][0], s[i][1]), fmaxf(s[i][2], s[i][3]));
#pragma unroll
            for (int o = 8; o > 0; o >>= 1)
                mt = fmaxf(mt, __shfl_xor_sync(0xffffffffu, mt, o, 16));
            float mnew = fmaxf(m_i[i], mt);
            float corr = __expf(m_i[i] - mnew);
            float ps = 0.f;
#pragma unroll
            for (int j = 0; j < 4; j++) {
                float p = __expf(s[i][j] - mnew);
                s[i][j] = p;
                ps += p;
            }
#pragma unroll
            for (int o = 8; o > 0; o >>= 1)
                ps += __shfl_xor_sync(0xffffffffu, ps, o, 16);
            l_i[i] = l_i[i] * corr + ps;
            m_i[i] = mnew;
#pragma unroll
            for (int j = 0; j < 4; j++) acc[i][j] *= corr;
        }

        __syncthreads();   // all Kt reads done before Ps (alias) writes
#pragma unroll
        for (int i = 0; i < 4; i++)
            *(float4*)&Ps[(i0 + i) * ASTRIDE + j0] =
                make_float4(s[i][0], s[i][1], s[i][2], s[i][3]);
        __syncthreads();

        // O += P @ V
#pragma unroll 4
        for (int k = 0; k < 64; k++) {
            float4 vf = *(const float4*)&Vs[k * ASTRIDE + j0];
            float p0 = Ps[(i0 + 0) * ASTRIDE + k];
            float p1 = Ps[(i0 + 1) * ASTRIDE + k];
            float p2 = Ps[(i0 + 2) * ASTRIDE + k];
            float p3 = Ps[(i0 + 3) * ASTRIDE + k];
            acc[0][0] += p0 * vf.x; acc[0][1] += p0 * vf.y; acc[0][2] += p0 * vf.z; acc[0][3] += p0 * vf.w;
            acc[1][0] += p1 * vf.x; acc[1][1] += p1 * vf.y; acc[1][2] += p1 * vf.z; acc[1][3] += p1 * vf.w;
            acc[2][0] += p2 * vf.x; acc[2][1] += p2 * vf.y; acc[2][2] += p2 * vf.z; acc[2][3] += p2 * vf.w;
            acc[3][0] += p3 * vf.x; acc[3][1] += p3 * vf.y; acc[3][2] += p3 * vf.z; acc[3][3] += p3 * vf.w;
        }
    }

    // epilogue: normalize, write ctx in [b][s][h*64+d] layout
#pragma unroll
    for (int i = 0; i < 4; i++) {
        float inv = 1.f / l_i[i];
        int row = qbase + i0 + i;
        float4 o = make_float4(acc[i][0] * inv, acc[i][1] * inv,
                               acc[i][2] * inv, acc[i][3] * inv);
        *(float4*)&g_ctx[((size_t)b * SS + row) * EE + h * 64 + j0] = o;
    }
}

// ---------------------------------------------------------------------------
// Launcher
// ---------------------------------------------------------------------------
extern "C" void kernel_launch(void* const* d_in, const int* in_sizes, int n_in,
                              void* d_out, int out_size) {
    const float* hs  = (const float*)d_in[0];
    const float* Wq  = (const float*)d_in[1];
    const float* bq  = (const float*)d_in[2];
    const float* Wk  = (const float*)d_in[3];
    const float* bk  = (const float*)d_in[4];
    const float* Wv  = (const float*)d_in[5];
    const float* bv  = (const float*)d_in[6];
    const float* Wo  = (const float*)d_in[7];
    const float* bo  = (const float*)d_in[8];
    const float* rel = (const float*)d_in[9];
    float* out = (float*)d_out;

    cudaFuncSetAttribute(attn_kernel,
                         cudaFuncAttributeMaxDynamicSharedMemorySize, ATTN_SMEM);

    // 1) bias table
    bias_kernel<<<(HH * SS + 255) / 256, 256>>>(rel);

    // 2) QKV projections
    dim3 ggrid(EE / GBN, (BB * SS) / GBM);   // (16, 32)
    gemm_kernel<<<ggrid, 256>>>(hs, Wq, bq, out, 1);
    gemm_kernel<<<ggrid, 256>>>(hs, Wk, bk, out, 2);
    gemm_kernel<<<ggrid, 256>>>(hs, Wv, bv, out, 3);

    // 3) attention
    dim3 agrid(SS / 64, HH, BB);             // (32, 16, 2)
    attn_kernel<<<agrid, 256, ATTN_SMEM>>>();

    // 4) output projection
    gemm_kernel<<<ggrid, 256>>>(hs, Wo, bo, out, 0);
}

// round 3
// speedup vs baseline: 1.2602x; 1.2602x over previous
#include <cuda_runtime.h>
#include <cuda_bf16.h>
#include <stdint.h>
#include <math.h>

#define BB 2
#define SS 2048
#define EE 1024
#define HH 16
#define DD 64
#define MTOT (BB*SS)

// ---------------------------------------------------------------------------
// Scratch (device globals — no allocation allowed)
// ---------------------------------------------------------------------------
__device__ float g_q[BB*HH*SS*DD];
__device__ float g_k[BB*HH*SS*DD];
__device__ float g_v[BB*HH*SS*DD];
__device__ float g_bias8[HH*SS];
__device__ __nv_bfloat16 g_ahi[MTOT*EE], g_alo[MTOT*EE];       // hs split
__device__ __nv_bfloat16 g_wthi[4u*EE*EE], g_wtlo[4u*EE*EE];   // W^T splits (q,k,v,o)
__device__ __nv_bfloat16 g_chi[MTOT*EE], g_clo[MTOT*EE];       // ctx split

// ---------------------------------------------------------------------------
// helpers
// ---------------------------------------------------------------------------
__device__ __forceinline__ uint32_t smem_u32(const void* p) {
    uint32_t r;
    asm("{ .reg .u64 t; cvta.to.shared.u64 t, %1; cvt.u32.u64 %0, t; }"
        : "=r"(r) : "l"(p));
    return r;
}

__device__ __forceinline__ void cp16(uint32_t dst, const void* src) {
    asm volatile("cp.async.cg.shared.global [%0], [%1], 16;"
                 :: "r"(dst), "l"(__cvta_generic_to_global(src)) : "memory");
}

__device__ __forceinline__ void mma_bf16(float* c, const uint32_t* a, const uint32_t* b) {
    asm volatile(
        "mma.sync.aligned.m16n8k16.row.col.f32.bf16.bf16.f32 "
        "{%0,%1,%2,%3}, {%4,%5,%6,%7}, {%8,%9}, {%0,%1,%2,%3};"
        : "+f"(c[0]), "+f"(c[1]), "+f"(c[2]), "+f"(c[3])
        : "r"(a[0]), "r"(a[1]), "r"(a[2]), "r"(a[3]), "r"(b[0]), "r"(b[1]));
}

// ---------------------------------------------------------------------------
// Kernel: position bias table
// ---------------------------------------------------------------------------
__global__ void bias_kernel(const float* __restrict__ rel_bias) {
    int idx = blockIdx.x * blockDim.x + threadIdx.x;
    if (idx >= HH * SS) return;
    int h = idx / SS;
    int d = idx % SS;
    int bucket;
    if (d < 16) {
        bucket = d;
    } else {
        float t = (logf((float)d * 0.0625f) / 1.3862943611198906f) * 16.0f;
        int lb = 16 + (int)t;
        bucket = lb < 31 ? lb : 31;
    }
    g_bias8[idx] = rel_bias[bucket * HH + h] * 8.0f;
}

// ---------------------------------------------------------------------------
// Kernel: split fp32 -> bf16 hi/lo (same layout)  [for hs]
// ---------------------------------------------------------------------------
__global__ void split_kernel(const float* __restrict__ in) {
    int i = blockIdx.x * blockDim.x + threadIdx.x;  // float4 index
    if (i >= MTOT * EE / 4) return;
    float4 v = ((const float4*)in)[i];
    __nv_bfloat16 h0 = __float2bfloat16(v.x);
    __nv_bfloat16 h1 = __float2bfloat16(v.y);
    __nv_bfloat16 h2 = __float2bfloat16(v.z);
    __nv_bfloat16 h3 = __float2bfloat16(v.w);
    __nv_bfloat16 l0 = __float2bfloat16(v.x - __bfloat162float(h0));
    __nv_bfloat16 l1 = __float2bfloat16(v.y - __bfloat162float(h1));
    __nv_bfloat16 l2 = __float2bfloat16(v.z - __bfloat162float(h2));
    __nv_bfloat16 l3 = __float2bfloat16(v.w - __bfloat162float(h3));
    __nv_bfloat162* hp = (__nv_bfloat162*)g_ahi + i * 2;
    __nv_bfloat162* lp = (__nv_bfloat162*)g_alo + i * 2;
    hp[0] = __halves2bfloat162(h0, h1);
    hp[1] = __halves2bfloat162(h2, h3);
    lp[0] = __halves2bfloat162(l0, l1);
    lp[1] = __halves2bfloat162(l2, l3);
}

// ---------------------------------------------------------------------------
// Kernel: transpose + split  W[K][N] fp32 -> WT[N][K] bf16 hi/lo
// ---------------------------------------------------------------------------
__global__ void wt_split_kernel(const float* __restrict__ W, int widx) {
    __shared__ float t[32][33];
    int n0 = blockIdx.x * 32, k0 = blockIdx.y * 32;
    int tx = threadIdx.x, ty = threadIdx.y;   // (32, 8)
#pragma unroll
    for (int i = 0; i < 4; i++)
        t[ty + i * 8][tx] = W[(size_t)(k0 + ty + i * 8) * EE + n0 + tx];
    __syncthreads();
    __nv_bfloat16* hi = g_wthi + (size_t)widx * EE * EE;
    __nv_bfloat16* lo = g_wtlo + (size_t)widx * EE * EE;
#pragma unroll
    for (int i = 0; i < 4; i++) {
        int n = n0 + ty + i * 8, k = k0 + tx;
        float v = t[tx][ty + i * 8];
        __nv_bfloat16 h = __float2bfloat16(v);
        __nv_bfloat16 l = __float2bfloat16(v - __bfloat162float(h));
        hi[(size_t)n * EE + k] = h;
        lo[(size_t)n * EE + k] = l;
    }
}

// ---------------------------------------------------------------------------
// Kernel: mma.sync bf16-split GEMM  C[4096,1024] = A @ W + bias
//   effective K = 3 segments x 1024:  Ahi*Bhi + Ahi*Blo + Alo*Bhi
//   mode 0: A = ctx split, out -> Cout [m][n]
//   mode 1/2/3: A = hs split, out scattered to g_q/g_k/g_v [b][h][s][d]
// ---------------------------------------------------------------------------
#define BM 128
#define BN 128
#define BKE 32
#define NSTAGE 4
#define RPAD 80                         // padded row pitch in bytes (40 bf16)
#define TILE_BYTES (128 * RPAD)         // 10240
#define STAGE_BYTES (2 * TILE_BYTES)    // A + B
#define GSMEM (NSTAGE * STAGE_BYTES)    // 81920
#define NITER 96                        // 3 segments * (1024/32)

__global__ __launch_bounds__(256, 1)
void gemm_mma(const float* __restrict__ bias, float* __restrict__ outp, int mode) {
    extern __shared__ char sm[];
    int tid = threadIdx.x;
    int lane = tid & 31, wid = tid >> 5;
    int wm = wid & 3, wn = wid >> 2;           // 4 m-warps x 2 n-warps
    int g = lane >> 2, tg = lane & 3;
    int m0 = blockIdx.y * BM, n0 = blockIdx.x * BN;

    const __nv_bfloat16* Ahi = (mode == 0) ? g_chi : g_ahi;
    const __nv_bfloat16* Alo = (mode == 0) ? g_clo : g_alo;
    int widx = (mode == 0) ? 3 : (mode - 1);
    const __nv_bfloat16* Bhi = g_wthi + (size_t)widx * EE * EE;
    const __nv_bfloat16* Blo = g_wtlo + (size_t)widx * EE * EE;

    float c[2][8][4];
#pragma unroll
    for (int mt = 0; mt < 2; mt++)
#pragma unroll
        for (int nt = 0; nt < 8; nt++)
#pragma unroll
            for (int i = 0; i < 4; i++) c[mt][nt][i] = 0.f;

    uint32_t smbase = smem_u32(sm);

    auto load_stage = [&](int git, int s) {
        int seg = git >> 5;
        int kb = (git & 31) * BKE;
        const __nv_bfloat16* Aseg = (seg == 2) ? Alo : Ahi;
        const __nv_bfloat16* Bseg = (seg == 1) ? Blo : Bhi;
        uint32_t As = smbase + s * STAGE_BYTES;
        uint32_t Bs = As + TILE_BYTES;
#pragma unroll
        for (int i = 0; i < 2; i++) {
            int ch = tid + i * 256;           // 0..511
            int m = ch >> 2, k16 = ch & 3;
            uint32_t off = m * RPAD + k16 * 16;
            cp16(As + off, Aseg + (size_t)(m0 + m) * EE + kb + k16 * 8);
            cp16(Bs + off, Bseg + (size_t)(n0 + m) * EE + kb + k16 * 8);
        }
    };

    // prologue: prefetch NSTAGE-1 stages
#pragma unroll
    for (int p = 0; p < NSTAGE - 1; p++) {
        load_stage(p, p);
        asm volatile("cp.async.commit_group;" ::: "memory");
    }

    for (int git = 0; git < NITER; git++) {
        asm volatile("cp.async.wait_group %0;" :: "n"(NSTAGE - 2) : "memory");
        __syncthreads();

        int nx = git + NSTAGE - 1;
        if (nx < NITER) load_stage(nx, nx & (NSTAGE - 1));
        asm volatile("cp.async.commit_group;" ::: "memory");

        const char* As = sm + (git & (NSTAGE - 1)) * STAGE_BYTES;
        const char* Bs = As + TILE_BYTES;
#pragma unroll
        for (int ks = 0; ks < 2; ks++) {
            int kb = ks * 32 + tg * 4;        // byte offset of k-pair
            uint32_t a[2][4], b[8][2];
#pragma unroll
            for (int mt = 0; mt < 2; mt++) {
                const char* base = As + (wm * 32 + mt * 16 + g) * RPAD;
                a[mt][0] = *(const uint32_t*)(base + kb);
                a[mt][1] = *(const uint32_t*)(base + 8 * RPAD + kb);
                a[mt][2] = *(const uint32_t*)(base + kb + 16);
                a[mt][3] = *(const uint32_t*)(base + 8 * RPAD + kb + 16);
            }
#pragma unroll
            for (int nt = 0; nt < 8; nt++) {
                const char* base = Bs + (wn * 64 + nt * 8 + g) * RPAD;
                b[nt][0] = *(const uint32_t*)(base + kb);
                b[nt][1] = *(const uint32_t*)(base + kb + 16);
            }
#pragma unroll
            for (int mt = 0; mt < 2; mt++)
#pragma unroll
                for (int nt = 0; nt < 8; nt++)
                    mma_bf16(c[mt][nt], a[mt], b[nt]);
        }
        __syncthreads();
    }

    // epilogue
    float* dstq = (mode == 1) ? g_q : (mode == 2) ? g_k : g_v;
#pragma unroll
    for (int mt = 0; mt < 2; mt++) {
#pragma unroll
        for (int nt = 0; nt < 8; nt++) {
            int n = n0 + wn * 64 + nt * 8 + 2 * tg;
            float bx = bias[n], by = bias[n + 1];
#pragma unroll
            for (int hh = 0; hh < 2; hh++) {
                int r = m0 + wm * 32 + mt * 16 + g + hh * 8;
                float2 o = make_float2(c[mt][nt][2 * hh] + bx,
                                       c[mt][nt][2 * hh + 1] + by);
                if (mode == 0) {
                    *(float2*)(outp + (size_t)r * EE + n) = o;
                } else {
                    int head = n >> 6, d = n & 63;
                    int bidx = r >> 11, srow = r & 2047;
                    *(float2*)(dstq + ((((size_t)bidx * HH + head) * SS + srow) * DD + d)) = o;
                }
            }
        }
    }
}

// ---------------------------------------------------------------------------
// Kernel: flash attention fp32 (epilogue writes ctx bf16 hi/lo split)
// ---------------------------------------------------------------------------
#define ASTRIDE 68
#define ATTN_SMEM (3 * 64 * ASTRIDE * 4)

__global__ __launch_bounds__(256)
void attn_kernel() {
    extern __shared__ float smem[];
    float* Qs = smem;
    float* Kt = smem + 64 * ASTRIDE;
    float* Vs = smem + 2 * 64 * ASTRIDE;
    float* Ps = Kt;

    int qt = blockIdx.x;
    int h  = blockIdx.y;
    int b  = blockIdx.z;
    int tid = threadIdx.x;
    int tx = tid & 15, ty = tid >> 4;
    int i0 = ty * 4, j0 = tx * 4;
    int qbase = qt * 64;

    const float* Qg = g_q + (((size_t)b * HH + h) * SS + qbase) * DD;
    const float* Kg = g_k + (((size_t)b * HH + h) * SS) * DD;
    const float* Vg = g_v + (((size_t)b * HH + h) * SS) * DD;
    const float* biasrow = g_bias8 + h * SS;

#pragma unroll
    for (int it = 0; it < 4; it++) {
        int idx = tid + it * 256;
        int r = idx >> 4;
        int c4 = idx & 15;
        float4 v = *(const float4*)&Qg[r * 64 + c4 * 4];
        v.x *= 0.125f; v.y *= 0.125f; v.z *= 0.125f; v.w *= 0.125f;
        *(float4*)&Qs[r * ASTRIDE + c4 * 4] = v;
    }

    float m_i[4], l_i[4], acc[4][4];
#pragma unroll
    for (int i = 0; i < 4; i++) {
        m_i[i] = -1e30f; l_i[i] = 0.f;
#pragma unroll
        for (int j = 0; j < 4; j++) acc[i][j] = 0.f;
    }

    for (int kt = 0; kt < 32; kt++) {
        __syncthreads();
#pragma unroll
        for (int it = 0; it < 4; it++) {
            int idx = tid + it * 256;
            int r = idx >> 4;
            int c4 = idx & 15;
            float4 kv = *(const float4*)&Kg[(size_t)(kt * 64 + r) * 64 + c4 * 4];
            Kt[(c4 * 4 + 0) * ASTRIDE + r] = kv.x;
            Kt[(c4 * 4 + 1) * ASTRIDE + r] = kv.y;
            Kt[(c4 * 4 + 2) * ASTRIDE + r] = kv.z;
            Kt[(c4 * 4 + 3) * ASTRIDE + r] = kv.w;
            float4 vv = *(const float4*)&Vg[(size_t)(kt * 64 + r) * 64 + c4 * 4];
            *(float4*)&Vs[r * ASTRIDE + c4 * 4] = vv;
        }
        __syncthreads();

        float s[4][4];
#pragma unroll
        for (int i = 0; i < 4; i++)
#pragma unroll
            for (int j = 0; j < 4; j++) s[i][j] = 0.f;

#pragma unroll 4
        for (int d = 0; d < 64; d++) {
            float4 kf = *(const float4*)&Kt[d * ASTRIDE + j0];
            float q0 = Qs[(i0 + 0) * ASTRIDE + d];
            float q1 = Qs[(i0 + 1) * ASTRIDE + d];
            float q2 = Qs[(i0 + 2) * ASTRIDE + d];
            float q3 = Qs[(i0 + 3) * ASTRIDE + d];
            s[0][0] += q0 * kf.x; s[0][1] += q0 * kf.y; s[0][2] += q0 * kf.z; s[0][3] += q0 * kf.w;
            s[1][0] += q1 * kf.x; s[1][1] += q1 * kf.y; s[1][2] += q1 * kf.z; s[1][3] += q1 * kf.w;
            s[2][0] += q2 * kf.x; s[2][1] += q2 * kf.y; s[2][2] += q2 * kf.z; s[2][3] += q2 * kf.w;
            s[3][0] += q3 * kf.x; s[3][1] += q3 * kf.y; s[3][2] += q3 * kf.z; s[3][3] += q3 * kf.w;
        }

#pragma unroll
        for (int i = 0; i < 4; i++) {
            int qrow = qbase + i0 + i;
#pragma unroll
            for (int j = 0; j < 4; j++) {
                int dist = qrow - (kt * 64 + j0 + j);
                if (dist < 0) dist = 0;
                s[i][j] += biasrow[dist];
            }
        }

#pragma unroll
        for (int i = 0; i < 4; i++) {
            float mt = fmaxf(fmaxf(s[i][0], s[i][1]), fmaxf(s[i][2], s[i][3]));
#pragma unroll
            for (int o = 8; o > 0; o >>= 1)
                mt = fmaxf(mt, __shfl_xor_sync(0xffffffffu, mt, o, 16));
            float mnew = fmaxf(m_i[i], mt);
            float corr = __expf(m_i[i] - mnew);
            float ps = 0.f;
#pragma unroll
            for (int j = 0; j < 4; j++) {
                float p = __expf(s[i][j] - mnew);
                s[i][j] = p;
                ps += p;
            }
#pragma unroll
            for (int o = 8; o > 0; o >>= 1)
                ps += __shfl_xor_sync(0xffffffffu, ps, o, 16);
            l_i[i] = l_i[i] * corr + ps;
            m_i[i] = mnew;
#pragma unroll
            for (int j = 0; j < 4; j++) acc[i][j] *= corr;
        }

        __syncthreads();
#pragma unroll
        for (int i = 0; i < 4; i++)
            *(float4*)&Ps[(i0 + i) * ASTRIDE + j0] =
                make_float4(s[i][0], s[i][1], s[i][2], s[i][3]);
        __syncthreads();

#pragma unroll 4
        for (int k = 0; k < 64; k++) {
            float4 vf = *(const float4*)&Vs[k * ASTRIDE + j0];
            float p0 = Ps[(i0 + 0) * ASTRIDE + k];
            float p1 = Ps[(i0 + 1) * ASTRIDE + k];
            float p2 = Ps[(i0 + 2) * ASTRIDE + k];
            float p3 = Ps[(i0 + 3) * ASTRIDE + k];
            acc[0][0] += p0 * vf.x; acc[0][1] += p0 * vf.y; acc[0][2] += p0 * vf.z; acc[0][3] += p0 * vf.w;
            acc[1][0] += p1 * vf.x; acc[1][1] += p1 * vf.y; acc[1][2] += p1 * vf.z; acc[1][3] += p1 * vf.w;
            acc[2][0] += p2 * vf.x; acc[2][1] += p2 * vf.y; acc[2][2] += p2 * vf.z; acc[2][3] += p2 * vf.w;
            acc[3][0] += p3 * vf.x; acc[3][1] += p3 * vf.y; acc[3][2] += p3 * vf.z; acc[3][3] += p3 * vf.w;
        }
    }

    // epilogue: normalize, split to bf16 hi/lo ctx
#pragma unroll
    for (int i = 0; i < 4; i++) {
        float inv = 1.f / l_i[i];
        int row = qbase + i0 + i;
        size_t base = ((size_t)b * SS + row) * EE + h * 64 + j0;
        float o0 = acc[i][0] * inv, o1 = acc[i][1] * inv;
        float o2 = acc[i][2] * inv, o3 = acc[i][3] * inv;
        __nv_bfloat16 h0 = __float2bfloat16(o0);
        __nv_bfloat16 h1 = __float2bfloat16(o1);
        __nv_bfloat16 h2 = __float2bfloat16(o2);
        __nv_bfloat16 h3 = __float2bfloat16(o3);
        __nv_bfloat16 l0 = __float2bfloat16(o0 - __bfloat162float(h0));
        __nv_bfloat16 l1 = __float2bfloat16(o1 - __bfloat162float(h1));
        __nv_bfloat16 l2 = __float2bfloat16(o2 - __bfloat162float(h2));
        __nv_bfloat16 l3 = __float2bfloat16(o3 - __bfloat162float(h3));
        *(__nv_bfloat162*)(g_chi + base)     = __halves2bfloat162(h0, h1);
        *(__nv_bfloat162*)(g_chi + base + 2) = __halves2bfloat162(h2, h3);
        *(__nv_bfloat162*)(g_clo + base)     = __halves2bfloat162(l0, l1);
        *(__nv_bfloat162*)(g_clo + base + 2) = __halves2bfloat162(l2, l3);
    }
}

// ---------------------------------------------------------------------------
// Launcher
// ---------------------------------------------------------------------------
extern "C" void kernel_launch(void* const* d_in, const int* in_sizes, int n_in,
                              void* d_out, int out_size) {
    const float* hs  = (const float*)d_in[0];
    const float* Wq  = (const float*)d_in[1];
    const float* bq  = (const float*)d_in[2];
    const float* Wk  = (const float*)d_in[3];
    const float* bk  = (const float*)d_in[4];
    const float* Wv  = (const float*)d_in[5];
    const float* bv  = (const float*)d_in[6];
    const float* Wo  = (const float*)d_in[7];
    const float* bo  = (const float*)d_in[8];
    const float* rel = (const float*)d_in[9];
    float* out = (float*)d_out;

    cudaFuncSetAttribute(gemm_mma, cudaFuncAttributeMaxDynamicSharedMemorySize, GSMEM);
    cudaFuncSetAttribute(attn_kernel, cudaFuncAttributeMaxDynamicSharedMemorySize, ATTN_SMEM);

    // 1) bias table + input/weight conversion
    bias_kernel<<<(HH * SS + 255) / 256, 256>>>(rel);
    split_kernel<<<(MTOT * EE / 4 + 255) / 256, 256>>>(hs);
    dim3 wgrid(32, 32), wblk(32, 8);
    wt_split_kernel<<<wgrid, wblk>>>(Wq, 0);
    wt_split_kernel<<<wgrid, wblk>>>(Wk, 1);
    wt_split_kernel<<<wgrid, wblk>>>(Wv, 2);
    wt_split_kernel<<<wgrid, wblk>>>(Wo, 3);

    // 2) QKV projections (tensor cores via mma.sync)
    dim3 ggrid(EE / BN, MTOT / BM);   // (8, 32)
    gemm_mma<<<ggrid, 256, GSMEM>>>(bq, out, 1);
    gemm_mma<<<ggrid, 256, GSMEM>>>(bk, out, 2);
    gemm_mma<<<ggrid, 256, GSMEM>>>(bv, out, 3);

    // 3) attention (fp32, writes ctx split)
    dim3 agrid(SS / 64, HH, BB);
    attn_kernel<<<agrid, 256, ATTN_SMEM>>>();

    // 4) output projection (tensor cores via mma.sync)
    gemm_mma<<<ggrid, 256, GSMEM>>>(bo, out, 0);
}

// round 4
// speedup vs baseline: 2.2200x; 1.7617x over previous
#include <cuda_runtime.h>
#include <cuda_bf16.h>
#include <stdint.h>
#include <math.h>

#define BB 2
#define SS 2048
#define EE 1024
#define HH 16
#define DD 64
#define MTOT (BB*SS)

// ---------------------------------------------------------------------------
// Scratch (device globals — no allocation allowed)
// ---------------------------------------------------------------------------
__device__ float g_bias8[HH*SS];
__device__ __nv_bfloat16 g_ahi[MTOT*EE], g_alo[MTOT*EE];       // hs split
__device__ __nv_bfloat16 g_wthi[4u*EE*EE], g_wtlo[4u*EE*EE];   // W^T splits
__device__ __nv_bfloat16 g_chi[MTOT*EE], g_clo[MTOT*EE];       // ctx split
__device__ __nv_bfloat16 g_qhi[BB*HH*SS*DD], g_qlo[BB*HH*SS*DD];   // [b][h][s][d], pre-scaled
__device__ __nv_bfloat16 g_khi[BB*HH*SS*DD], g_klo[BB*HH*SS*DD];   // [b][h][s][d]
__device__ __nv_bfloat16 g_vthi[BB*HH*SS*DD], g_vtlo[BB*HH*SS*DD]; // [b][h][d][s] (transposed)

// ---------------------------------------------------------------------------
// helpers
// ---------------------------------------------------------------------------
__device__ __forceinline__ uint32_t smem_u32(const void* p) {
    uint32_t r;
    asm("{ .reg .u64 t; cvta.to.shared.u64 t, %1; cvt.u32.u64 %0, t; }"
        : "=r"(r) : "l"(p));
    return r;
}

__device__ __forceinline__ void cp16(uint32_t dst, const void* src) {
    asm volatile("cp.async.cg.shared.global [%0], [%1], 16;"
                 :: "r"(dst), "l"(__cvta_generic_to_global(src)) : "memory");
}

__device__ __forceinline__ void mma_bf16(float* c, const uint32_t* a, const uint32_t* b) {
    asm volatile(
        "mma.sync.aligned.m16n8k16.row.col.f32.bf16.bf16.f32 "
        "{%0,%1,%2,%3}, {%4,%5,%6,%7}, {%8,%9}, {%0,%1,%2,%3};"
        : "+f"(c[0]), "+f"(c[1]), "+f"(c[2]), "+f"(c[3])
        : "r"(a[0]), "r"(a[1]), "r"(a[2]), "r"(a[3]), "r"(b[0]), "r"(b[1]));
}

__device__ __forceinline__ uint32_t lds32(uint32_t addr) {
    uint32_t v;
    asm volatile("ld.shared.b32 %0, [%1];" : "=r"(v) : "r"(addr));
    return v;
}

// pack {lo=a, hi=b} as bf16x2
__device__ __forceinline__ uint32_t pack_bf16x2(float a, float b) {
    uint32_t d;
    asm("cvt.rn.bf16x2.f32 %0, %1, %2;" : "=r"(d) : "f"(b), "f"(a));
    return d;
}
// residual pack: given floats and their hi-pack, produce lo-pack
__device__ __forceinline__ uint32_t pack_resid(float a, float b, uint32_t hi) {
    float fa = __uint_as_float(hi << 16);
    float fb = __uint_as_float(hi & 0xffff0000u);
    return pack_bf16x2(a - fa, b - fb);
}

// ---------------------------------------------------------------------------
// bias table
// ---------------------------------------------------------------------------
__global__ void bias_kernel(const float* __restrict__ rel_bias) {
    int idx = blockIdx.x * blockDim.x + threadIdx.x;
    if (idx >= HH * SS) return;
    int h = idx / SS;
    int d = idx % SS;
    int bucket;
    if (d < 16) {
        bucket = d;
    } else {
        float t = (logf((float)d * 0.0625f) / 1.3862943611198906f) * 16.0f;
        int lb = 16 + (int)t;
        bucket = lb < 31 ? lb : 31;
    }
    g_bias8[idx] = rel_bias[bucket * HH + h] * 8.0f;
}

// ---------------------------------------------------------------------------
// split fp32 -> bf16 hi/lo for hs
// ---------------------------------------------------------------------------
__global__ void split_kernel(const float* __restrict__ in) {
    int i = blockIdx.x * blockDim.x + threadIdx.x;
    if (i >= MTOT * EE / 4) return;
    float4 v = ((const float4*)in)[i];
    uint32_t h01 = pack_bf16x2(v.x, v.y), h23 = pack_bf16x2(v.z, v.w);
    uint32_t l01 = pack_resid(v.x, v.y, h01), l23 = pack_resid(v.z, v.w, h23);
    ((uint32_t*)g_ahi)[i * 2] = h01;  ((uint32_t*)g_ahi)[i * 2 + 1] = h23;
    ((uint32_t*)g_alo)[i * 2] = l01;  ((uint32_t*)g_alo)[i * 2 + 1] = l23;
}

// ---------------------------------------------------------------------------
// transpose + split weights
// ---------------------------------------------------------------------------
__global__ void wt_split_kernel(const float* __restrict__ W, int widx) {
    __shared__ float t[32][33];
    int n0 = blockIdx.x * 32, k0 = blockIdx.y * 32;
    int tx = threadIdx.x, ty = threadIdx.y;
#pragma unroll
    for (int i = 0; i < 4; i++)
        t[ty + i * 8][tx] = W[(size_t)(k0 + ty + i * 8) * EE + n0 + tx];
    __syncthreads();
    __nv_bfloat16* hi = g_wthi + (size_t)widx * EE * EE;
    __nv_bfloat16* lo = g_wtlo + (size_t)widx * EE * EE;
#pragma unroll
    for (int i = 0; i < 4; i++) {
        int n = n0 + ty + i * 8, k = k0 + tx;
        float v = t[tx][ty + i * 8];
        __nv_bfloat16 h = __float2bfloat16(v);
        __nv_bfloat16 l = __float2bfloat16(v - __bfloat162float(h));
        hi[(size_t)n * EE + k] = h;
        lo[(size_t)n * EE + k] = l;
    }
}

// ---------------------------------------------------------------------------
// mma.sync bf16-split GEMM  C[4096,1024] = A @ W + bias
//   mode 0: A = ctx split, out -> Cout fp32 [m][n]
//   mode 1: -> Q split (scaled 0.125) [b][h][s][d]
//   mode 2: -> K split [b][h][s][d]
//   mode 3: -> V split transposed [b][h][d][s]
// ---------------------------------------------------------------------------
#define BM 128
#define BN 128
#define BKE 32
#define NSTAGE 4
#define RPAD 80
#define TILE_BYTES (128 * RPAD)
#define STAGE_BYTES (2 * TILE_BYTES)
#define GSMEM (NSTAGE * STAGE_BYTES)
#define NITER 96

__global__ __launch_bounds__(256, 1)
void gemm_mma(const float* __restrict__ bias, float* __restrict__ outp, int mode) {
    extern __shared__ char sm[];
    int tid = threadIdx.x;
    int lane = tid & 31, wid = tid >> 5;
    int wm = wid & 3, wn = wid >> 2;
    int g = lane >> 2, tg = lane & 3;
    int m0 = blockIdx.y * BM, n0 = blockIdx.x * BN;

    const __nv_bfloat16* Ahi = (mode == 0) ? g_chi : g_ahi;
    const __nv_bfloat16* Alo = (mode == 0) ? g_clo : g_alo;
    int widx = (mode == 0) ? 3 : (mode - 1);
    const __nv_bfloat16* Bhi = g_wthi + (size_t)widx * EE * EE;
    const __nv_bfloat16* Blo = g_wtlo + (size_t)widx * EE * EE;

    float c[2][8][4];
#pragma unroll
    for (int mt = 0; mt < 2; mt++)
#pragma unroll
        for (int nt = 0; nt < 8; nt++)
#pragma unroll
            for (int i = 0; i < 4; i++) c[mt][nt][i] = 0.f;

    uint32_t smbase = smem_u32(sm);

    auto load_stage = [&](int git, int s) {
        int seg = git >> 5;
        int kb = (git & 31) * BKE;
        const __nv_bfloat16* Aseg = (seg == 2) ? Alo : Ahi;
        const __nv_bfloat16* Bseg = (seg == 1) ? Blo : Bhi;
        uint32_t As = smbase + s * STAGE_BYTES;
        uint32_t Bs = As + TILE_BYTES;
#pragma unroll
        for (int i = 0; i < 2; i++) {
            int ch = tid + i * 256;
            int m = ch >> 2, k16 = ch & 3;
            uint32_t off = m * RPAD + k16 * 16;
            cp16(As + off, Aseg + (size_t)(m0 + m) * EE + kb + k16 * 8);
            cp16(Bs + off, Bseg + (size_t)(n0 + m) * EE + kb + k16 * 8);
        }
    };

#pragma unroll
    for (int p = 0; p < NSTAGE - 1; p++) {
        load_stage(p, p);
        asm volatile("cp.async.commit_group;" ::: "memory");
    }

    for (int git = 0; git < NITER; git++) {
        asm volatile("cp.async.wait_group %0;" :: "n"(NSTAGE - 2) : "memory");
        __syncthreads();

        int nx = git + NSTAGE - 1;
        if (nx < NITER) load_stage(nx, nx & (NSTAGE - 1));
        asm volatile("cp.async.commit_group;" ::: "memory");

        const char* As = sm + (git & (NSTAGE - 1)) * STAGE_BYTES;
        const char* Bs = As + TILE_BYTES;
#pragma unroll
        for (int ks = 0; ks < 2; ks++) {
            int kb = ks * 32 + tg * 4;
            uint32_t a[2][4], b[8][2];
#pragma unroll
            for (int mt = 0; mt < 2; mt++) {
                const char* base = As + (wm * 32 + mt * 16 + g) * RPAD;
                a[mt][0] = *(const uint32_t*)(base + kb);
                a[mt][1] = *(const uint32_t*)(base + 8 * RPAD + kb);
                a[mt][2] = *(const uint32_t*)(base + kb + 16);
                a[mt][3] = *(const uint32_t*)(base + 8 * RPAD + kb + 16);
            }
#pragma unroll
            for (int nt = 0; nt < 8; nt++) {
                const char* base = Bs + (wn * 64 + nt * 8 + g) * RPAD;
                b[nt][0] = *(const uint32_t*)(base + kb);
                b[nt][1] = *(const uint32_t*)(base + kb + 16);
            }
#pragma unroll
            for (int mt = 0; mt < 2; mt++)
#pragma unroll
                for (int nt = 0; nt < 8; nt++)
                    mma_bf16(c[mt][nt], a[mt], b[nt]);
        }
        __syncthreads();
    }

    // epilogue
#pragma unroll
    for (int mt = 0; mt < 2; mt++) {
#pragma unroll
        for (int nt = 0; nt < 8; nt++) {
            int n = n0 + wn * 64 + nt * 8 + 2 * tg;
            float bx = bias[n], by = bias[n + 1];
#pragma unroll
            for (int hh = 0; hh < 2; hh++) {
                int r = m0 + wm * 32 + mt * 16 + g + hh * 8;
                float vx = c[mt][nt][2 * hh] + bx;
                float vy = c[mt][nt][2 * hh + 1] + by;
                if (mode == 0) {
                    *(float2*)(outp + (size_t)r * EE + n) = make_float2(vx, vy);
                } else {
                    if (mode == 1) { vx *= 0.125f; vy *= 0.125f; }
                    uint32_t hp = pack_bf16x2(vx, vy);
                    uint32_t lp = pack_resid(vx, vy, hp);
                    int head = n >> 6, d = n & 63;
                    int bidx = r >> 11, srow = r & 2047;
                    size_t bh = (size_t)bidx * HH + head;
                    if (mode == 3) {
                        size_t i0 = (bh * DD + d) * SS + srow;
                        size_t i1 = (bh * DD + d + 1) * SS + srow;
                        g_vthi[i0] = __ushort_as_bfloat16((unsigned short)(hp & 0xffff));
                        g_vthi[i1] = __ushort_as_bfloat16((unsigned short)(hp >> 16));
                        g_vtlo[i0] = __ushort_as_bfloat16((unsigned short)(lp & 0xffff));
                        g_vtlo[i1] = __ushort_as_bfloat16((unsigned short)(lp >> 16));
                    } else {
                        size_t idx = (bh * SS + srow) * DD + d;
                        __nv_bfloat16* dh = (mode == 1) ? g_qhi : g_khi;
                        __nv_bfloat16* dl = (mode == 1) ? g_qlo : g_klo;
                        *(uint32_t*)(dh + idx) = hp;
                        *(uint32_t*)(dl + idx) = lp;
                    }
                }
            }
        }
    }
}

// ---------------------------------------------------------------------------
// tensor-core flash attention, bf16-split, m16n8k16
//   CTA = (q-tile 128, head, batch); 8 warps x 16 q-rows; k-tiles of 64.
// ---------------------------------------------------------------------------
#define QT 128
#define KT 64
#define PITCH 144                       // 64 bf16 = 128B, padded
#define KV_TILE (KT * PITCH)            // 9216
#define KV_STAGE (4 * KV_TILE)          // Khi,Klo,Vhi,Vlo = 36864
#define OFF_QHI 8192
#define OFF_QLO (OFF_QHI + QT * PITCH)  // 26624
#define OFF_ST  (OFF_QLO + QT * PITCH)  // 45056
#define ATTN_SMEM (OFF_ST + 2 * KV_STAGE)  // 118784

__global__ __launch_bounds__(256, 1)
void attn_tc() {
    extern __shared__ char sm[];
    float* bias_s = (float*)sm;
    uint32_t smb = smem_u32(sm);
    int tid = threadIdx.x, lane = tid & 31, w = tid >> 5;
    int g = lane >> 2, tg = lane & 3;
    int qt = blockIdx.x, h = blockIdx.y, b = blockIdx.z;
    int q0 = qt * QT;
    size_t bh = (size_t)b * HH + h;

    const __nv_bfloat16* Khi = g_khi + bh * SS * DD;
    const __nv_bfloat16* Klo = g_klo + bh * SS * DD;
    const __nv_bfloat16* Vhi = g_vthi + bh * DD * SS;
    const __nv_bfloat16* Vlo = g_vtlo + bh * DD * SS;
    const __nv_bfloat16* Qhi = g_qhi + (bh * SS + q0) * DD;
    const __nv_bfloat16* Qlo = g_qlo + (bh * SS + q0) * DD;

    // bias row -> smem
    const float4* br = (const float4*)(g_bias8 + h * SS);
    for (int i = tid; i < SS / 4; i += 256) ((float4*)bias_s)[i] = br[i];

    // stage Q tiles + KV stage 0 (one cp.async group)
#pragma unroll
    for (int i = 0; i < 4; i++) {
        int ch = tid + i * 256;             // 0..1023
        int r = ch >> 3, cc = ch & 7;
        uint32_t off = r * PITCH + cc * 16;
        cp16(smb + OFF_QHI + off, Qhi + r * 64 + cc * 8);
        cp16(smb + OFF_QLO + off, Qlo + r * 64 + cc * 8);
    }
    auto load_kv = [&](int kt, int s) {
        uint32_t base = smb + OFF_ST + s * KV_STAGE;
        int k0 = kt * KT;
#pragma unroll
        for (int i = 0; i < 2; i++) {
            int ch = tid + i * 256;         // 0..511
            int r = ch >> 3, cc = ch & 7;
            uint32_t off = r * PITCH + cc * 16;
            cp16(base + off,               Khi + (size_t)(k0 + r) * 64 + cc * 8);
            cp16(base + KV_TILE + off,     Klo + (size_t)(k0 + r) * 64 + cc * 8);
            cp16(base + 2 * KV_TILE + off, Vhi + (size_t)r * SS + k0 + cc * 8);
            cp16(base + 3 * KV_TILE + off, Vlo + (size_t)r * SS + k0 + cc * 8);
        }
    };
    load_kv(0, 0);
    asm volatile("cp.async.commit_group;" ::: "memory");

    float m0 = -1e30f, m1 = -1e30f, l0 = 0.f, l1 = 0.f;
    float acc[8][4];
#pragma unroll
    for (int j = 0; j < 8; j++)
#pragma unroll
        for (int i = 0; i < 4; i++) acc[j][i] = 0.f;

    uint32_t qh[16], ql[16];
    int qrow0 = q0 + w * 16 + g;
    int qrow1 = qrow0 + 8;

    for (int kt = 0; kt < 32; kt++) {
        __syncthreads();                    // buffer-reuse guard
        if (kt + 1 < 32) load_kv(kt + 1, (kt + 1) & 1);
        asm volatile("cp.async.commit_group;" ::: "memory");
        asm volatile("cp.async.wait_group 1;" ::: "memory");
        __syncthreads();

        if (kt == 0) {
            // load Q A-frags once
#pragma unroll
            for (int s = 0; s < 4; s++) {
                uint32_t bse = smb + OFF_QHI + (w * 16 + g) * PITCH + tg * 4 + s * 32;
                qh[4*s+0] = lds32(bse);
                qh[4*s+1] = lds32(bse + 8 * PITCH);
                qh[4*s+2] = lds32(bse + 16);
                qh[4*s+3] = lds32(bse + 8 * PITCH + 16);
                uint32_t bsl = bse + (OFF_QLO - OFF_QHI);
                ql[4*s+0] = lds32(bsl);
                ql[4*s+1] = lds32(bsl + 8 * PITCH);
                ql[4*s+2] = lds32(bsl + 16);
                ql[4*s+3] = lds32(bsl + 8 * PITCH + 16);
            }
        }

        uint32_t stg = smb + OFF_ST + (kt & 1) * KV_STAGE;
        uint32_t kbase = stg + g * PITCH + tg * 4;

        // ---- S = Q K^T (3-term split) ----
        float sc[8][4];
#pragma unroll
        for (int j = 0; j < 8; j++)
#pragma unroll
            for (int i = 0; i < 4; i++) sc[j][i] = 0.f;

#pragma unroll
        for (int j = 0; j < 8; j++) {
#pragma unroll
            for (int s = 0; s < 4; s++) {
                uint32_t addr = kbase + j * (8 * PITCH) + s * 32;
                uint32_t bhi[2] = { lds32(addr), lds32(addr + 16) };
                uint32_t blo[2] = { lds32(addr + KV_TILE), lds32(addr + KV_TILE + 16) };
                mma_bf16(sc[j], &qh[4*s], bhi);
                mma_bf16(sc[j], &ql[4*s], bhi);
                mma_bf16(sc[j], &qh[4*s], blo);
            }
        }

        // ---- bias add ----
        int colb = kt * KT + 2 * tg;
#pragma unroll
        for (int j = 0; j < 8; j++) {
            int col = colb + 8 * j;
            int d0 = qrow0 - col, d1 = qrow1 - col;
            sc[j][0] += bias_s[max(d0, 0)];
            sc[j][1] += bias_s[max(d0 - 1, 0)];
            sc[j][2] += bias_s[max(d1, 0)];
            sc[j][3] += bias_s[max(d1 - 1, 0)];
        }

        // ---- online softmax ----
        float mt0 = sc[0][0], mt1 = sc[0][2];
#pragma unroll
        for (int j = 0; j < 8; j++) {
            mt0 = fmaxf(mt0, fmaxf(sc[j][0], sc[j][1]));
            mt1 = fmaxf(mt1, fmaxf(sc[j][2], sc[j][3]));
        }
        mt0 = fmaxf(mt0, __shfl_xor_sync(0xffffffffu, mt0, 1));
        mt0 = fmaxf(mt0, __shfl_xor_sync(0xffffffffu, mt0, 2));
        mt1 = fmaxf(mt1, __shfl_xor_sync(0xffffffffu, mt1, 1));
        mt1 = fmaxf(mt1, __shfl_xor_sync(0xffffffffu, mt1, 2));
        float mn0 = fmaxf(m0, mt0), mn1 = fmaxf(m1, mt1);
        float cr0 = __expf(m0 - mn0), cr1 = __expf(m1 - mn1);
        float ps0 = 0.f, ps1 = 0.f;
#pragma unroll
        for (int j = 0; j < 8; j++) {
            sc[j][0] = __expf(sc[j][0] - mn0);
            sc[j][1] = __expf(sc[j][1] - mn0);
            sc[j][2] = __expf(sc[j][2] - mn1);
            sc[j][3] = __expf(sc[j][3] - mn1);
            ps0 += sc[j][0] + sc[j][1];
            ps1 += sc[j][2] + sc[j][3];
        }
        ps0 += __shfl_xor_sync(0xffffffffu, ps0, 1);
        ps0 += __shfl_xor_sync(0xffffffffu, ps0, 2);
        ps1 += __shfl_xor_sync(0xffffffffu, ps1, 1);
        ps1 += __shfl_xor_sync(0xffffffffu, ps1, 2);
        l0 = l0 * cr0 + ps0;  m0 = mn0;
        l1 = l1 * cr1 + ps1;  m1 = mn1;
#pragma unroll
        for (int j = 0; j < 8; j++) {
            acc[j][0] *= cr0; acc[j][1] *= cr0;
            acc[j][2] *= cr1; acc[j][3] *= cr1;
        }

        // ---- P -> bf16 hi/lo fragments (C-frag == A-frag identity) ----
        uint32_t ph[8], ph2[8], pl[8], pl2[8];
#pragma unroll
        for (int j = 0; j < 8; j++) {
            ph[j]  = pack_bf16x2(sc[j][0], sc[j][1]);
            pl[j]  = pack_resid(sc[j][0], sc[j][1], ph[j]);
            ph2[j] = pack_bf16x2(sc[j][2], sc[j][3]);
            pl2[j] = pack_resid(sc[j][2], sc[j][3], ph2[j]);
        }

        // ---- O += P V (3-term split) ----
        uint32_t vbase = stg + 2 * KV_TILE + g * PITCH + tg * 4;
#pragma unroll
        for (int j = 0; j < 8; j++) {
#pragma unroll
            for (int s = 0; s < 4; s++) {
                uint32_t addr = vbase + j * (8 * PITCH) + s * 32;
                uint32_t vh[2] = { lds32(addr), lds32(addr + 16) };
                uint32_t vl[2] = { lds32(addr + KV_TILE), lds32(addr + KV_TILE + 16) };
                uint32_t pA[4] = { ph[2*s], ph2[2*s], ph[2*s+1], ph2[2*s+1] };
                uint32_t pL[4] = { pl[2*s], pl2[2*s], pl[2*s+1], pl2[2*s+1] };
                mma_bf16(acc[j], pA, vh);
                mma_bf16(acc[j], pL, vh);
                mma_bf16(acc[j], pA, vl);
            }
        }
    }

    // ---- epilogue: normalize, write ctx split ----
    float inv0 = 1.f / l0, inv1 = 1.f / l1;
#pragma unroll
    for (int j = 0; j < 8; j++) {
        int e = h * 64 + 8 * j + 2 * tg;
        {
            float ox = acc[j][0] * inv0, oy = acc[j][1] * inv0;
            uint32_t hp = pack_bf16x2(ox, oy);
            uint32_t lp = pack_resid(ox, oy, hp);
            size_t base = ((size_t)b * SS + qrow0) * EE + e;
            *(uint32_t*)(g_chi + base) = hp;
            *(uint32_t*)(g_clo + base) = lp;
        }
        {
            float ox = acc[j][2] * inv1, oy = acc[j][3] * inv1;
            uint32_t hp = pack_bf16x2(ox, oy);
            uint32_t lp = pack_resid(ox, oy, hp);
            size_t base = ((size_t)b * SS + qrow1) * EE + e;
            *(uint32_t*)(g_chi + base) = hp;
            *(uint32_t*)(g_clo + base) = lp;
        }
    }
}

// ---------------------------------------------------------------------------
// Launcher
// ---------------------------------------------------------------------------
extern "C" void kernel_launch(void* const* d_in, const int* in_sizes, int n_in,
                              void* d_out, int out_size) {
    const float* hs  = (const float*)d_in[0];
    const float* Wq  = (const float*)d_in[1];
    const float* bq  = (const float*)d_in[2];
    const float* Wk  = (const float*)d_in[3];
    const float* bk  = (const float*)d_in[4];
    const float* Wv  = (const float*)d_in[5];
    const float* bv  = (const float*)d_in[6];
    const float* Wo  = (const float*)d_in[7];
    const float* bo  = (const float*)d_in[8];
    const float* rel = (const float*)d_in[9];
    float* out = (float*)d_out;

    cudaFuncSetAttribute(gemm_mma, cudaFuncAttributeMaxDynamicSharedMemorySize, GSMEM);
    cudaFuncSetAttribute(attn_tc, cudaFuncAttributeMaxDynamicSharedMemorySize, ATTN_SMEM);

    bias_kernel<<<(HH * SS + 255) / 256, 256>>>(rel);
    split_kernel<<<(MTOT * EE / 4 + 255) / 256, 256>>>(hs);
    dim3 wgrid(32, 32), wblk(32, 8);
    wt_split_kernel<<<wgrid, wblk>>>(Wq, 0);
    wt_split_kernel<<<wgrid, wblk>>>(Wk, 1);
    wt_split_kernel<<<wgrid, wblk>>>(Wv, 2);
    wt_split_kernel<<<wgrid, wblk>>>(Wo, 3);

    dim3 ggrid(EE / BN, MTOT / BM);
    gemm_mma<<<ggrid, 256, GSMEM>>>(bq, out, 1);
    gemm_mma<<<ggrid, 256, GSMEM>>>(bk, out, 2);
    gemm_mma<<<ggrid, 256, GSMEM>>>(bv, out, 3);

    dim3 agrid(SS / QT, HH, BB);   // (16, 16, 2)
    attn_tc<<<agrid, 256, ATTN_SMEM>>>();

    gemm_mma<<<ggrid, 256, GSMEM>>>(bo, out, 0);
}